// round 8
// baseline (speedup 1.0000x reference)
#include <cuda_runtime.h>
#include <cuda_bf16.h>
#include <cstdint>
#include <math.h>

// Problem constants
#define PIXELS 8192      // B*H*W = 8*32*32
#define DD 512
#define FF 32
#define NN 16384
#define HWSZ 1024
#define SPLITS 8
#define CPS (NN / SPLITS)   // 2048 codes per split
#define KS2 128             // 4 split blocks of 32 along K
#define XSTR2 136           // staging row stride in bf16 (conflict-free)
#define CH 64               // codes per chunk in kernel C

// Output layout (concatenated flattened outputs, float32):
#define OUT_OFF      0
#define CLOSEST_OFF  4194304
#define LOSS_OFF     4202496
#define PERP_OFF     4202497

// Scratch (no allocations allowed)
__device__ float g_xn[PIXELS * FF];       // normalized projected x, [p][32]
__device__ float g_en[NN * FF];           // normalized codebook, [n][32]
__device__ __nv_bfloat16 g_xsplit[PIXELS * KS2]; // linear [xh|xh|xm|xm]
// g_esplit is FRAGMENT-ordered: [code-group of 8][kt 0..7][lane 0..31][4 bf16]
// lane = (code%8)*4 + ((k%8)>>1); elem = (k%16>=8)*2 + (k&1)
__device__ __nv_bfloat16 g_esplit[NN * KS2];
__device__ float g_pval[SPLITS * PIXELS]; // per-split best value
__device__ int   g_pidx[SPLITS * PIXELS]; // per-split best index
__device__ int   g_closest[PIXELS];
__device__ int   g_hist[NN];
__device__ float g_lossp[PIXELS];

// exact fp32 -> bf16 x2 split (hi + mid)
__device__ __forceinline__ void split2(float v, __nv_bfloat16& b0,
                                       __nv_bfloat16& b1)
{
    b0 = __float2bfloat16_rn(v);
    float r1 = v - __bfloat162float(b0);
    b1 = __float2bfloat16_rn(r1);
}

// ---------------------------------------------------------------------------
// Kernel A: 1x1 conv projection + channel L2 normalize + linear split layout.
// ---------------------------------------------------------------------------
__global__ void proj_norm_kernel(const float* __restrict__ enc,
                                 const float* __restrict__ pw,
                                 const float* __restrict__ pb)
{
    extern __shared__ float sm[];
    float* Ws  = sm;                 // 32*512
    float* xsh = sm + FF * DD;       // 32*33 (padded)
    float* nrm = xsh + 32 * 33;      // 32

    int tid = threadIdx.x;

    const float4* W4 = (const float4*)pw;
    float4* Ws4 = (float4*)Ws;
#pragma unroll
    for (int i = 0; i < 16; i++) Ws4[tid + 256 * i] = W4[tid + 256 * i];
    __syncthreads();

    int lane = tid & 31;     // pixel within tile
    int fg   = tid >> 5;     // 0..7
    int f0   = fg * 4;
    int p    = blockIdx.x * 32 + lane;
    int b    = p >> 10;
    int hw   = p & 1023;

    const float* ep = enc + (size_t)b * DD * HWSZ + hw;
    const float4* w0 = (const float4*)(Ws + (size_t)(f0 + 0) * DD);
    const float4* w1 = (const float4*)(Ws + (size_t)(f0 + 1) * DD);
    const float4* w2 = (const float4*)(Ws + (size_t)(f0 + 2) * DD);
    const float4* w3 = (const float4*)(Ws + (size_t)(f0 + 3) * DD);

    float a0 = 0.f, a1 = 0.f, a2 = 0.f, a3 = 0.f;
#pragma unroll 4
    for (int q = 0; q < 128; q++) {
        float e0 = ep[(4 * q + 0) * HWSZ];
        float e1 = ep[(4 * q + 1) * HWSZ];
        float e2 = ep[(4 * q + 2) * HWSZ];
        float e3 = ep[(4 * q + 3) * HWSZ];
        float4 W0 = w0[q], W1 = w1[q], W2 = w2[q], W3 = w3[q];
        a0 += e0 * W0.x; a0 += e1 * W0.y; a0 += e2 * W0.z; a0 += e3 * W0.w;
        a1 += e0 * W1.x; a1 += e1 * W1.y; a1 += e2 * W1.z; a1 += e3 * W1.w;
        a2 += e0 * W2.x; a2 += e1 * W2.y; a2 += e2 * W2.z; a2 += e3 * W2.w;
        a3 += e0 * W3.x; a3 += e1 * W3.y; a3 += e2 * W3.z; a3 += e3 * W3.w;
    }
    a0 += pb[f0 + 0];
    a1 += pb[f0 + 1];
    a2 += pb[f0 + 2];
    a3 += pb[f0 + 3];

    xsh[lane * 33 + f0 + 0] = a0;
    xsh[lane * 33 + f0 + 1] = a1;
    xsh[lane * 33 + f0 + 2] = a2;
    xsh[lane * 33 + f0 + 3] = a3;
    __syncthreads();

    if (tid < 32) {
        float ss = 0.f;
#pragma unroll
        for (int f = 0; f < 32; f++) { float v = xsh[tid * 33 + f]; ss += v * v; }
        nrm[tid] = fmaxf(sqrtf(ss), 1e-6f);
    }
    __syncthreads();

    float nm = nrm[lane];
    float o[4] = { a0 / nm, a1 / nm, a2 / nm, a3 / nm };
    *(float4*)(g_xn + (size_t)p * FF + f0) = *(float4*)o;

    // X split blocks (linear): [xh | xh | xm | xm]
    __nv_bfloat16* xr = g_xsplit + (size_t)p * KS2;
#pragma unroll
    for (int k = 0; k < 4; k++) {
        __nv_bfloat16 h, m;
        split2(o[k], h, m);
        int f = f0 + k;
        xr[f]       = h;
        xr[32 + f]  = h;
        xr[64 + f]  = m;
        xr[96 + f]  = m;
    }
}

// ---------------------------------------------------------------------------
// Kernel B: codebook L2 normalize + FRAGMENT-ordered split store.
// ---------------------------------------------------------------------------
__device__ __forceinline__ void efrag_store(int r, int k_eff, __nv_bfloat16 v)
{
    int kt  = k_eff >> 4;
    int kr  = k_eff & 15;
    int fl  = (r & 7) * 4 + ((kr & 7) >> 1);
    int el  = (kr >> 3) * 2 + (kr & 1);
    g_esplit[(size_t)(r >> 3) * 1024 + kt * 128 + fl * 4 + el] = v;
}

__global__ void enorm_kernel(const float* __restrict__ emb)
{
    int tid  = threadIdx.x;
    int r    = blockIdx.x * 8 + (tid >> 5);
    int lane = tid & 31;
    float v = emb[(size_t)r * 32 + lane];
    float ss = v * v;
#pragma unroll
    for (int o = 16; o; o >>= 1) ss += __shfl_xor_sync(0xffffffffu, ss, o);
    float nm = fmaxf(sqrtf(ss), 1e-6f);
    float en = v / nm;
    g_en[(size_t)r * 32 + lane] = en;

    // E split blocks: [eh | em | eh | em] in fragment order
    __nv_bfloat16 h, m;
    split2(en, h, m);
    efrag_store(r, lane, h);
    efrag_store(r, 32 + lane, m);
    efrag_store(r, 64 + lane, h);
    efrag_store(r, 96 + lane, m);
}

// ---------------------------------------------------------------------------
// Kernel H: zero histogram (keeps sims in ncu's captured launch slot)
// ---------------------------------------------------------------------------
__global__ void histzero_kernel()
{
    g_hist[blockIdx.x * 256 + threadIdx.x] = 0;
}

// ---------------------------------------------------------------------------
// mma.sync m16n8k16 row.col bf16 -> f32
// ---------------------------------------------------------------------------
__device__ __forceinline__ void mma16816(float* c, const uint32_t* a,
                                         uint32_t b0, uint32_t b1)
{
    asm volatile(
        "mma.sync.aligned.m16n8k16.row.col.f32.bf16.bf16.f32 "
        "{%0,%1,%2,%3}, {%4,%5,%6,%7}, {%8,%9}, {%0,%1,%2,%3};"
        : "+f"(c[0]), "+f"(c[1]), "+f"(c[2]), "+f"(c[3])
        : "r"(a[0]), "r"(a[1]), "r"(a[2]), "r"(a[3]), "r"(b0), "r"(b1));
}

// ---------------------------------------------------------------------------
// Kernel C (dominant): bf16 4-term split cosine sims on tensor cores.
// 256 thr (8 warps), warp tile 16 px, A operand held in 32 registers for the
// whole kernel; B frags are single LDS.64 from fragment-ordered smem.
// Block tile 128 px x 64-code chunks; grid (64 px-tiles, 8 splits).
// ---------------------------------------------------------------------------
__global__ void __launch_bounds__(256, 2) sims_argmax_kernel()
{
    extern __shared__ __nv_bfloat16 smc[];   // 128*XSTR2 staging, reused as es

    int tid  = threadIdx.x;
    int wid  = tid >> 5;
    int lane = tid & 31;
    int g    = lane >> 2;   // row group (pixel rows g, g+8) / B column
    int kq   = lane & 3;    // k quad
    int px0  = blockIdx.x * 128;
    int cbase = blockIdx.y * CPS;

    // stage x tile linear: 128 rows x 16 uint4 (256B/row)
    for (int i = tid; i < 128 * 16; i += 256) {
        int r = i >> 4, q = i & 15;
        ((uint4*)(smc + r * XSTR2))[q] =
            ((const uint4*)(g_xsplit + (size_t)(px0 + r) * KS2))[q];
    }
    __syncthreads();

    // extract A fragments once (held in registers across all chunks)
    uint32_t A[8][4];
    {
        int r0 = wid * 16 + g;
#pragma unroll
        for (int kt = 0; kt < 8; kt++) {
            int k0 = kt * 16 + kq * 2;
            A[kt][0] = *(const uint32_t*)(smc + r0 * XSTR2 + k0);
            A[kt][1] = *(const uint32_t*)(smc + (r0 + 8) * XSTR2 + k0);
            A[kt][2] = *(const uint32_t*)(smc + r0 * XSTR2 + k0 + 8);
            A[kt][3] = *(const uint32_t*)(smc + (r0 + 8) * XSTR2 + k0 + 8);
        }
    }
    __syncthreads();   // staging buffer now reusable as es

    __nv_bfloat16* es = smc;   // fragment-ordered chunk: [8 groups][8 kt][256B]

    float bv[2];
    int   bi[2];
#pragma unroll
    for (int s = 0; s < 2; s++) { bv[s] = -3.4e38f; bi[s] = 0; }

    for (int ch = 0; ch < CPS; ch += CH) {
        __syncthreads();
        // linear 16KB copy (fragment order is contiguous per 64-code chunk)
        {
            const uint4* src = (const uint4*)(g_esplit + (size_t)(cbase + ch) * KS2);
            for (int i = tid; i < 1024; i += 256)
                ((uint4*)es)[i] = src[i];
        }
        __syncthreads();

        float acc[8][4];
#pragma unroll
        for (int nt = 0; nt < 8; nt++)
#pragma unroll
            for (int c = 0; c < 4; c++) acc[nt][c] = 0.f;

#pragma unroll
        for (int kt = 0; kt < 8; kt++) {
#pragma unroll
            for (int nt = 0; nt < 8; nt++) {
                uint2 bb = *(const uint2*)(es + nt * 1024 + kt * 128 + lane * 4);
                mma16816(acc[nt], A[kt], bb.x, bb.y);
            }
        }

        // argmax update; code indices ascend (chunk, nt, col pair) so strict >
        // keeps first occurrence within this lane
#pragma unroll
        for (int nt = 0; nt < 8; nt++) {
            int c0 = cbase + ch + nt * 8 + kq * 2;
            // row g
            if (acc[nt][0] > bv[0]) { bv[0] = acc[nt][0]; bi[0] = c0; }
            if (acc[nt][1] > bv[0]) { bv[0] = acc[nt][1]; bi[0] = c0 + 1; }
            // row g+8
            if (acc[nt][2] > bv[1]) { bv[1] = acc[nt][2]; bi[1] = c0; }
            if (acc[nt][3] > bv[1]) { bv[1] = acc[nt][3]; bi[1] = c0 + 1; }
        }
    }

    // reduce across the 4 kq lanes of each row group (lower index wins ties)
#pragma unroll
    for (int s = 0; s < 2; s++) {
#pragma unroll
        for (int o = 1; o <= 2; o <<= 1) {
            float ov = __shfl_xor_sync(0xffffffffu, bv[s], o);
            int   oi = __shfl_xor_sync(0xffffffffu, bi[s], o);
            if (ov > bv[s] || (ov == bv[s] && oi < bi[s])) { bv[s] = ov; bi[s] = oi; }
        }
    }
    if (kq == 0) {
#pragma unroll
        for (int s = 0; s < 2; s++) {
            int p = px0 + wid * 16 + s * 8 + g;
            g_pval[blockIdx.y * PIXELS + p] = bv[s];
            g_pidx[blockIdx.y * PIXELS + p] = bi[s];
        }
    }
}

// ---------------------------------------------------------------------------
// Kernel F: reduce split partials -> closest; histogram; per-pixel loss partial.
// ---------------------------------------------------------------------------
__global__ void reduce_kernel(float* __restrict__ out)
{
    int p = blockIdx.x * 256 + threadIdx.x;
    float bv = -3.4e38f;
    int   bi = 0x7fffffff;
#pragma unroll
    for (int s = 0; s < SPLITS; s++) {
        float v = g_pval[s * PIXELS + p];
        int  ix = g_pidx[s * PIXELS + p];
        if (v > bv || (v == bv && ix < bi)) { bv = v; bi = ix; }
    }
    g_closest[p] = bi;
    out[CLOSEST_OFF + p] = (float)bi;
    atomicAdd(&g_hist[bi], 1);

    float s2 = 0.f;
    const float4* xr = (const float4*)(g_xn + (size_t)p * 32);
    const float4* er = (const float4*)(g_en + (size_t)bi * 32);
#pragma unroll
    for (int q = 0; q < 8; q++) {
        float4 x = xr[q], e = er[q];
        float d0 = x.x - e.x, d1 = x.y - e.y, d2 = x.z - e.z, d3 = x.w - e.w;
        s2 += d0 * d0; s2 += d1 * d1; s2 += d2 * d2; s2 += d3 * d3;
    }
    g_lossp[p] = s2;
}

// ---------------------------------------------------------------------------
// Kernel D: expansion GEMM: out[b,d,hw] = sum_f lat[p][f] * exp_w[d][f] + exp_b[d]
// ---------------------------------------------------------------------------
__global__ void expand_kernel(const float* __restrict__ ew,
                              const float* __restrict__ eb,
                              float* __restrict__ out)
{
    __shared__ float Wsh[64 * 32];
    __shared__ float bsh[64];
    int tid = threadIdx.x;
    int d0  = blockIdx.y * 64;

    const float4* src = (const float4*)(ew + (size_t)d0 * 32);
    float4* dst = (float4*)Wsh;
    dst[tid]       = src[tid];
    dst[tid + 256] = src[tid + 256];
    if (tid < 64) bsh[tid] = eb[d0 + tid];
    __syncthreads();

    int p  = blockIdx.x * 256 + tid;
    int b  = p >> 10;
    int hw = p & 1023;
    int idx = g_closest[p];

    float4 lat[8];
    const float4* lr = (const float4*)(g_en + (size_t)idx * 32);
#pragma unroll
    for (int q = 0; q < 8; q++) lat[q] = lr[q];

    float* outp = out + OUT_OFF + ((size_t)b * 512 + d0) * 1024 + hw;
#pragma unroll 2
    for (int dd = 0; dd < 64; dd++) {
        const float4* wr = (const float4*)(Wsh + dd * 32);
        float s = bsh[dd];
#pragma unroll
        for (int q = 0; q < 8; q++) {
            float4 w = wr[q];
            s += lat[q].x * w.x; s += lat[q].y * w.y;
            s += lat[q].z * w.z; s += lat[q].w * w.w;
        }
        outp[(size_t)dd * 1024] = s;
    }
}

// ---------------------------------------------------------------------------
// Kernel G: deterministic final reductions -> loss_q, perplexity
// ---------------------------------------------------------------------------
__global__ void finalize_kernel(float* __restrict__ out)
{
    __shared__ double sh[256];
    int tid = threadIdx.x;

    double ls = 0.0;
    for (int i = tid; i < PIXELS; i += 256) ls += (double)g_lossp[i];
    sh[tid] = ls;
    __syncthreads();
    for (int o = 128; o; o >>= 1) {
        if (tid < o) sh[tid] += sh[tid + o];
        __syncthreads();
    }
    double loss = sh[0] / (double)(PIXELS * 32);
    __syncthreads();

    double ps = 0.0;
    for (int i = tid; i < NN; i += 256) {
        float u = (float)g_hist[i] * (1.0f / 8192.0f);
        ps += -(double)u * log((double)u + 1e-6);
    }
    sh[tid] = ps;
    __syncthreads();
    for (int o = 128; o; o >>= 1) {
        if (tid < o) sh[tid] += sh[tid + o];
        __syncthreads();
    }
    if (tid == 0) {
        out[LOSS_OFF] = (float)loss;
        out[PERP_OFF] = (float)exp(sh[0]);
    }
}

// ---------------------------------------------------------------------------
extern "C" void kernel_launch(void* const* d_in, const int* in_sizes, int n_in,
                              void* d_out, int out_size)
{
    const float* enc = (const float*)d_in[0];  // [8,512,32,32]
    const float* emb = (const float*)d_in[1];  // [16384,32]
    const float* pw  = (const float*)d_in[2];  // [32,512]
    const float* pb  = (const float*)d_in[3];  // [32]
    const float* ew  = (const float*)d_in[4];  // [512,32]
    const float* eb  = (const float*)d_in[5];  // [512]
    float* out = (float*)d_out;

    (void)in_sizes; (void)n_in; (void)out_size;

    const int a_smem = (FF * DD + 32 * 33 + 32) * (int)sizeof(float); // 69888
    cudaFuncSetAttribute(proj_norm_kernel,
                         cudaFuncAttributeMaxDynamicSharedMemorySize, a_smem);

    const int c_smem = 128 * XSTR2 * (int)sizeof(__nv_bfloat16); // 34816
    cudaFuncSetAttribute(sims_argmax_kernel,
                         cudaFuncAttributeMaxDynamicSharedMemorySize, c_smem);

    proj_norm_kernel<<<256, 256, a_smem>>>(enc, pw, pb);
    enorm_kernel<<<2048, 256>>>(emb);
    histzero_kernel<<<64, 256>>>();
    sims_argmax_kernel<<<dim3(64, SPLITS), 256, c_smem>>>();
    reduce_kernel<<<32, 256>>>(out);
    expand_kernel<<<dim3(32, 8), 256>>>(ew, eb, out);
    finalize_kernel<<<1, 256>>>(out);
}

// round 9
// speedup vs baseline: 1.1782x; 1.1782x over previous
#include <cuda_runtime.h>
#include <cuda_bf16.h>
#include <cstdint>
#include <math.h>

// Problem constants
#define PIXELS 8192      // B*H*W = 8*32*32
#define DD 512
#define FF 32
#define NN 16384
#define HWSZ 1024
#define SPLITS 8
#define CPS (NN / SPLITS)   // 2048 codes per split
#define KS2 128             // 4 split blocks of 32 along K
#define XSTR2 136           // staging row stride in bf16 (conflict-free)
#define CH 64               // codes per chunk in kernel C

// Output layout (concatenated flattened outputs, float32):
#define OUT_OFF      0
#define CLOSEST_OFF  4194304
#define LOSS_OFF     4202496
#define PERP_OFF     4202497

// Scratch (no allocations allowed)
__device__ float g_xn[PIXELS * FF];       // normalized projected x, [p][32]
__device__ float g_en[NN * FF];           // normalized codebook, [n][32]
__device__ __nv_bfloat16 g_xsplit[PIXELS * KS2]; // linear [xh|xh|xm|xm]
// g_esplit is FRAGMENT-ordered: [code-group of 8][kt 0..7][lane 0..31][4 bf16]
__device__ __nv_bfloat16 g_esplit[NN * KS2];
__device__ float g_pval[SPLITS * PIXELS]; // per-split best value
__device__ int   g_pidx[SPLITS * PIXELS]; // per-split best index
__device__ int   g_closest[PIXELS];
__device__ int   g_hist[NN];
__device__ float g_lossp[PIXELS];

// exact fp32 -> bf16 x2 split (hi + mid)
__device__ __forceinline__ void split2(float v, __nv_bfloat16& b0,
                                       __nv_bfloat16& b1)
{
    b0 = __float2bfloat16_rn(v);
    float r1 = v - __bfloat162float(b0);
    b1 = __float2bfloat16_rn(r1);
}

// ---------------------------------------------------------------------------
// Kernel A: 1x1 conv projection + channel L2 normalize + linear split layout.
// ---------------------------------------------------------------------------
__global__ void proj_norm_kernel(const float* __restrict__ enc,
                                 const float* __restrict__ pw,
                                 const float* __restrict__ pb)
{
    extern __shared__ float sm[];
    float* Ws  = sm;                 // 32*512
    float* xsh = sm + FF * DD;       // 32*33 (padded)
    float* nrm = xsh + 32 * 33;      // 32

    int tid = threadIdx.x;

    const float4* W4 = (const float4*)pw;
    float4* Ws4 = (float4*)Ws;
#pragma unroll
    for (int i = 0; i < 16; i++) Ws4[tid + 256 * i] = W4[tid + 256 * i];
    __syncthreads();

    int lane = tid & 31;     // pixel within tile
    int fg   = tid >> 5;     // 0..7
    int f0   = fg * 4;
    int p    = blockIdx.x * 32 + lane;
    int b    = p >> 10;
    int hw   = p & 1023;

    const float* ep = enc + (size_t)b * DD * HWSZ + hw;
    const float4* w0 = (const float4*)(Ws + (size_t)(f0 + 0) * DD);
    const float4* w1 = (const float4*)(Ws + (size_t)(f0 + 1) * DD);
    const float4* w2 = (const float4*)(Ws + (size_t)(f0 + 2) * DD);
    const float4* w3 = (const float4*)(Ws + (size_t)(f0 + 3) * DD);

    float a0 = 0.f, a1 = 0.f, a2 = 0.f, a3 = 0.f;
#pragma unroll 4
    for (int q = 0; q < 128; q++) {
        float e0 = ep[(4 * q + 0) * HWSZ];
        float e1 = ep[(4 * q + 1) * HWSZ];
        float e2 = ep[(4 * q + 2) * HWSZ];
        float e3 = ep[(4 * q + 3) * HWSZ];
        float4 W0 = w0[q], W1 = w1[q], W2 = w2[q], W3 = w3[q];
        a0 += e0 * W0.x; a0 += e1 * W0.y; a0 += e2 * W0.z; a0 += e3 * W0.w;
        a1 += e0 * W1.x; a1 += e1 * W1.y; a1 += e2 * W1.z; a1 += e3 * W1.w;
        a2 += e0 * W2.x; a2 += e1 * W2.y; a2 += e2 * W2.z; a2 += e3 * W2.w;
        a3 += e0 * W3.x; a3 += e1 * W3.y; a3 += e2 * W3.z; a3 += e3 * W3.w;
    }
    a0 += pb[f0 + 0];
    a1 += pb[f0 + 1];
    a2 += pb[f0 + 2];
    a3 += pb[f0 + 3];

    xsh[lane * 33 + f0 + 0] = a0;
    xsh[lane * 33 + f0 + 1] = a1;
    xsh[lane * 33 + f0 + 2] = a2;
    xsh[lane * 33 + f0 + 3] = a3;
    __syncthreads();

    if (tid < 32) {
        float ss = 0.f;
#pragma unroll
        for (int f = 0; f < 32; f++) { float v = xsh[tid * 33 + f]; ss += v * v; }
        nrm[tid] = fmaxf(sqrtf(ss), 1e-6f);
    }
    __syncthreads();

    float nm = nrm[lane];
    float o[4] = { a0 / nm, a1 / nm, a2 / nm, a3 / nm };
    *(float4*)(g_xn + (size_t)p * FF + f0) = *(float4*)o;

    // X split blocks (linear): [xh | xh | xm | xm]
    __nv_bfloat16* xr = g_xsplit + (size_t)p * KS2;
#pragma unroll
    for (int k = 0; k < 4; k++) {
        __nv_bfloat16 h, m;
        split2(o[k], h, m);
        int f = f0 + k;
        xr[f]       = h;
        xr[32 + f]  = h;
        xr[64 + f]  = m;
        xr[96 + f]  = m;
    }
}

// ---------------------------------------------------------------------------
// Kernel B: codebook L2 normalize + FRAGMENT-ordered split store.
// ---------------------------------------------------------------------------
__device__ __forceinline__ void efrag_store(int r, int k_eff, __nv_bfloat16 v)
{
    int kt  = k_eff >> 4;
    int kr  = k_eff & 15;
    int fl  = (r & 7) * 4 + ((kr & 7) >> 1);
    int el  = (kr >> 3) * 2 + (kr & 1);
    g_esplit[(size_t)(r >> 3) * 1024 + kt * 128 + fl * 4 + el] = v;
}

__global__ void enorm_kernel(const float* __restrict__ emb)
{
    int tid  = threadIdx.x;
    int r    = blockIdx.x * 8 + (tid >> 5);
    int lane = tid & 31;
    float v = emb[(size_t)r * 32 + lane];
    float ss = v * v;
#pragma unroll
    for (int o = 16; o; o >>= 1) ss += __shfl_xor_sync(0xffffffffu, ss, o);
    float nm = fmaxf(sqrtf(ss), 1e-6f);
    float en = v / nm;
    g_en[(size_t)r * 32 + lane] = en;

    __nv_bfloat16 h, m;
    split2(en, h, m);
    efrag_store(r, lane, h);
    efrag_store(r, 32 + lane, m);
    efrag_store(r, 64 + lane, h);
    efrag_store(r, 96 + lane, m);
}

// ---------------------------------------------------------------------------
// Kernel H: zero histogram (keeps sims in ncu's captured launch slot)
// ---------------------------------------------------------------------------
__global__ void histzero_kernel()
{
    g_hist[blockIdx.x * 256 + threadIdx.x] = 0;
}

// ---------------------------------------------------------------------------
// mma.sync m16n8k16 row.col bf16 -> f32
// ---------------------------------------------------------------------------
__device__ __forceinline__ void mma16816(float* c, const uint32_t* a,
                                         uint32_t b0, uint32_t b1)
{
    asm volatile(
        "mma.sync.aligned.m16n8k16.row.col.f32.bf16.bf16.f32 "
        "{%0,%1,%2,%3}, {%4,%5,%6,%7}, {%8,%9}, {%0,%1,%2,%3};"
        : "+f"(c[0]), "+f"(c[1]), "+f"(c[2]), "+f"(c[3])
        : "r"(a[0]), "r"(a[1]), "r"(a[2]), "r"(a[3]), "r"(b0), "r"(b1));
}

__device__ __forceinline__ uint32_t smem_u32c(const void* p) {
    uint32_t a;
    asm("{ .reg .u64 t; cvta.to.shared.u64 t, %1; cvt.u32.u64 %0, t; }"
        : "=r"(a) : "l"(p));
    return a;
}

// ---------------------------------------------------------------------------
// Kernel C (dominant): bf16 4-term split cosine sims on tensor cores.
// 256 thr = 4 pixel-quarter warps x 2 code-half warps. Warp tile 32px x 32
// codes: each B frag (LDS.64) feeds 2 mmas -> smem 1 cyc/mma vs tensor 2.
// A held in 64 regs for the whole kernel. E chunks cp.async double-buffered.
// Block tile 128 px x 64-code chunks; grid (64 px-tiles, 8 splits).
// ---------------------------------------------------------------------------
__global__ void __launch_bounds__(256, 2) sims_argmax_kernel()
{
    extern __shared__ __nv_bfloat16 smc[];   // 34816B: staging, then 2x16KB bufs + merge

    int tid  = threadIdx.x;
    int wid  = tid >> 5;
    int lane = tid & 31;
    int g    = lane >> 2;   // row group / B column
    int kq   = lane & 3;    // k quad
    int cw   = wid >> 2;    // code half (0: codes 0-31 of chunk, 1: 32-63)
    int mw   = wid & 3;     // pixel quarter (32 px each)
    int px0  = blockIdx.x * 128;
    int cbase = blockIdx.y * CPS;

    // stage x tile linear: 128 rows x 16 uint4 (256B/row)
    for (int i = tid; i < 128 * 16; i += 256) {
        int r = i >> 4, q = i & 15;
        ((uint4*)(smc + r * XSTR2))[q] =
            ((const uint4*)(g_xsplit + (size_t)(px0 + r) * KS2))[q];
    }
    __syncthreads();

    // extract A fragments once: A[kt][mt][4], held in registers throughout
    uint32_t A[8][2][4];
#pragma unroll
    for (int kt = 0; kt < 8; kt++) {
        int k0 = kt * 16 + kq * 2;
#pragma unroll
        for (int mt = 0; mt < 2; mt++) {
            int r0 = mw * 32 + mt * 16 + g;
            A[kt][mt][0] = *(const uint32_t*)(smc + r0 * XSTR2 + k0);
            A[kt][mt][1] = *(const uint32_t*)(smc + (r0 + 8) * XSTR2 + k0);
            A[kt][mt][2] = *(const uint32_t*)(smc + r0 * XSTR2 + k0 + 8);
            A[kt][mt][3] = *(const uint32_t*)(smc + (r0 + 8) * XSTR2 + k0 + 8);
        }
    }
    __syncthreads();   // staging dead; reuse as double buffers

    uint32_t buf_base = smem_u32c(smc);   // buf0 @ +0, buf1 @ +16384 bytes

    // preload chunk 0 into buf0 via cp.async (each thread copies 4x16B)
    {
        const char* src = (const char*)(g_esplit + (size_t)cbase * KS2);
#pragma unroll
        for (int j = 0; j < 4; j++) {
            uint32_t d = buf_base + (tid + 256 * j) * 16;
            asm volatile("cp.async.ca.shared.global [%0], [%1], 16;"
                         :: "r"(d), "l"(src + (tid + 256 * j) * 16) : "memory");
        }
        asm volatile("cp.async.commit_group;" ::: "memory");
    }

    float bv[4];
    int   bi[4];
#pragma unroll
    for (int s = 0; s < 4; s++) { bv[s] = -3.4e38f; bi[s] = 0; }

    for (int ch = 0; ch < CPS; ch += CH) {
        int cur = (ch >> 6) & 1;
        // all warps done reading buf[cur^1] (prev iter) before overwriting it
        __syncthreads();
        if (ch + CH < CPS) {
            const char* src = (const char*)(g_esplit + (size_t)(cbase + ch + CH) * KS2);
            uint32_t dbase = buf_base + (cur ^ 1) * 16384;
#pragma unroll
            for (int j = 0; j < 4; j++) {
                uint32_t d = dbase + (tid + 256 * j) * 16;
                asm volatile("cp.async.ca.shared.global [%0], [%1], 16;"
                             :: "r"(d), "l"(src + (tid + 256 * j) * 16) : "memory");
            }
            asm volatile("cp.async.commit_group;" ::: "memory");
            asm volatile("cp.async.wait_group 1;" ::: "memory");
        } else {
            asm volatile("cp.async.wait_group 0;" ::: "memory");
        }
        __syncthreads();   // chunk cur fully visible

        const __nv_bfloat16* es = smc + cur * 8192 + cw * 4096;  // this half's 4 groups

        float acc[4][2][4];
#pragma unroll
        for (int nt = 0; nt < 4; nt++)
#pragma unroll
            for (int mt = 0; mt < 2; mt++)
#pragma unroll
                for (int c = 0; c < 4; c++) acc[nt][mt][c] = 0.f;

#pragma unroll
        for (int kt = 0; kt < 8; kt++) {
#pragma unroll
            for (int nt = 0; nt < 4; nt++) {
                uint2 bb = *(const uint2*)(es + nt * 1024 + kt * 128 + lane * 4);
                mma16816(acc[nt][0], A[kt][0], bb.x, bb.y);
                mma16816(acc[nt][1], A[kt][1], bb.x, bb.y);
            }
        }

        // argmax update; code indices ascend within this warp's half
#pragma unroll
        for (int nt = 0; nt < 4; nt++) {
            int c0 = cbase + ch + cw * 32 + nt * 8 + kq * 2;
#pragma unroll
            for (int mt = 0; mt < 2; mt++) {
#pragma unroll
                for (int h = 0; h < 2; h++) {
                    int s = mt * 2 + h;
                    float v0 = acc[nt][mt][h * 2 + 0];
                    float v1 = acc[nt][mt][h * 2 + 1];
                    if (v0 > bv[s]) { bv[s] = v0; bi[s] = c0; }
                    if (v1 > bv[s]) { bv[s] = v1; bi[s] = c0 + 1; }
                }
            }
        }
    }

    // reduce across the 4 kq lanes (lower index wins ties)
#pragma unroll
    for (int s = 0; s < 4; s++) {
#pragma unroll
        for (int o = 1; o <= 2; o <<= 1) {
            float ov = __shfl_xor_sync(0xffffffffu, bv[s], o);
            int   oi = __shfl_xor_sync(0xffffffffu, bi[s], o);
            if (ov > bv[s] || (ov == bv[s] && oi < bi[s])) { bv[s] = ov; bi[s] = oi; }
        }
    }

    // merge the two code-half warps per pixel via smem (bytes 32768..34816)
    float* sv = (float*)((char*)smc + 32768);   // [2][128]
    int*   si = (int*)(sv + 256);               // [2][128]
    __syncthreads();
    if (kq == 0) {
#pragma unroll
        for (int s = 0; s < 4; s++) {
            int mt = s >> 1, h = s & 1;
            int pix = mw * 32 + mt * 16 + h * 8 + g;
            sv[cw * 128 + pix] = bv[s];
            si[cw * 128 + pix] = bi[s];
        }
    }
    __syncthreads();
    if (tid < 128) {
        float v0 = sv[tid];       int i0 = si[tid];
        float v1 = sv[128 + tid]; int i1 = si[128 + tid];
        if (v1 > v0 || (v1 == v0 && i1 < i0)) { v0 = v1; i0 = i1; }
        g_pval[blockIdx.y * PIXELS + px0 + tid] = v0;
        g_pidx[blockIdx.y * PIXELS + px0 + tid] = i0;
    }
}

// ---------------------------------------------------------------------------
// Kernel F: reduce split partials -> closest; histogram; per-pixel loss partial.
// ---------------------------------------------------------------------------
__global__ void reduce_kernel(float* __restrict__ out)
{
    int p = blockIdx.x * 256 + threadIdx.x;
    float bv = -3.4e38f;
    int   bi = 0x7fffffff;
#pragma unroll
    for (int s = 0; s < SPLITS; s++) {
        float v = g_pval[s * PIXELS + p];
        int  ix = g_pidx[s * PIXELS + p];
        if (v > bv || (v == bv && ix < bi)) { bv = v; bi = ix; }
    }
    g_closest[p] = bi;
    out[CLOSEST_OFF + p] = (float)bi;
    atomicAdd(&g_hist[bi], 1);

    float s2 = 0.f;
    const float4* xr = (const float4*)(g_xn + (size_t)p * 32);
    const float4* er = (const float4*)(g_en + (size_t)bi * 32);
#pragma unroll
    for (int q = 0; q < 8; q++) {
        float4 x = xr[q], e = er[q];
        float d0 = x.x - e.x, d1 = x.y - e.y, d2 = x.z - e.z, d3 = x.w - e.w;
        s2 += d0 * d0; s2 += d1 * d1; s2 += d2 * d2; s2 += d3 * d3;
    }
    g_lossp[p] = s2;
}

// ---------------------------------------------------------------------------
// Kernel D: expansion GEMM: out[b,d,hw] = sum_f lat[p][f] * exp_w[d][f] + exp_b[d]
// ---------------------------------------------------------------------------
__global__ void expand_kernel(const float* __restrict__ ew,
                              const float* __restrict__ eb,
                              float* __restrict__ out)
{
    __shared__ float Wsh[64 * 32];
    __shared__ float bsh[64];
    int tid = threadIdx.x;
    int d0  = blockIdx.y * 64;

    const float4* src = (const float4*)(ew + (size_t)d0 * 32);
    float4* dst = (float4*)Wsh;
    dst[tid]       = src[tid];
    dst[tid + 256] = src[tid + 256];
    if (tid < 64) bsh[tid] = eb[d0 + tid];
    __syncthreads();

    int p  = blockIdx.x * 256 + tid;
    int b  = p >> 10;
    int hw = p & 1023;
    int idx = g_closest[p];

    float4 lat[8];
    const float4* lr = (const float4*)(g_en + (size_t)idx * 32);
#pragma unroll
    for (int q = 0; q < 8; q++) lat[q] = lr[q];

    float* outp = out + OUT_OFF + ((size_t)b * 512 + d0) * 1024 + hw;
#pragma unroll 2
    for (int dd = 0; dd < 64; dd++) {
        const float4* wr = (const float4*)(Wsh + dd * 32);
        float s = bsh[dd];
#pragma unroll
        for (int q = 0; q < 8; q++) {
            float4 w = wr[q];
            s += lat[q].x * w.x; s += lat[q].y * w.y;
            s += lat[q].z * w.z; s += lat[q].w * w.w;
        }
        outp[(size_t)dd * 1024] = s;
    }
}

// ---------------------------------------------------------------------------
// Kernel G: deterministic final reductions -> loss_q, perplexity
// ---------------------------------------------------------------------------
__global__ void finalize_kernel(float* __restrict__ out)
{
    __shared__ double sh[256];
    int tid = threadIdx.x;

    double ls = 0.0;
    for (int i = tid; i < PIXELS; i += 256) ls += (double)g_lossp[i];
    sh[tid] = ls;
    __syncthreads();
    for (int o = 128; o; o >>= 1) {
        if (tid < o) sh[tid] += sh[tid + o];
        __syncthreads();
    }
    double loss = sh[0] / (double)(PIXELS * 32);
    __syncthreads();

    double ps = 0.0;
    for (int i = tid; i < NN; i += 256) {
        float u = (float)g_hist[i] * (1.0f / 8192.0f);
        ps += -(double)u * log((double)u + 1e-6);
    }
    sh[tid] = ps;
    __syncthreads();
    for (int o = 128; o; o >>= 1) {
        if (tid < o) sh[tid] += sh[tid + o];
        __syncthreads();
    }
    if (tid == 0) {
        out[LOSS_OFF] = (float)loss;
        out[PERP_OFF] = (float)exp(sh[0]);
    }
}

// ---------------------------------------------------------------------------
extern "C" void kernel_launch(void* const* d_in, const int* in_sizes, int n_in,
                              void* d_out, int out_size)
{
    const float* enc = (const float*)d_in[0];  // [8,512,32,32]
    const float* emb = (const float*)d_in[1];  // [16384,32]
    const float* pw  = (const float*)d_in[2];  // [32,512]
    const float* pb  = (const float*)d_in[3];  // [32]
    const float* ew  = (const float*)d_in[4];  // [512,32]
    const float* eb  = (const float*)d_in[5];  // [512]
    float* out = (float*)d_out;

    (void)in_sizes; (void)n_in; (void)out_size;

    const int a_smem = (FF * DD + 32 * 33 + 32) * (int)sizeof(float); // 69888
    cudaFuncSetAttribute(proj_norm_kernel,
                         cudaFuncAttributeMaxDynamicSharedMemorySize, a_smem);

    const int c_smem = 128 * XSTR2 * (int)sizeof(__nv_bfloat16); // 34816
    cudaFuncSetAttribute(sims_argmax_kernel,
                         cudaFuncAttributeMaxDynamicSharedMemorySize, c_smem);

    proj_norm_kernel<<<256, 256, a_smem>>>(enc, pw, pb);
    enorm_kernel<<<2048, 256>>>(emb);
    histzero_kernel<<<64, 256>>>();
    sims_argmax_kernel<<<dim3(64, SPLITS), 256, c_smem>>>();
    reduce_kernel<<<32, 256>>>(out);
    expand_kernel<<<dim3(32, 8), 256>>>(ew, eb, out);
    finalize_kernel<<<1, 256>>>(out);
}

// round 10
// speedup vs baseline: 1.2827x; 1.0888x over previous
#include <cuda_runtime.h>
#include <cuda_fp16.h>
#include <cstdint>
#include <math.h>

// Problem constants
#define PIXELS 8192      // B*H*W = 8*32*32
#define DD 512
#define FF 32
#define NN 16384
#define HWSZ 1024
#define SPLITS 8
#define CPS (NN / SPLITS)   // 2048 codes per split
#define KS3 96              // 3 split blocks of 32 along K (fp16 2-term split)
#define NKT 6               // k16 steps
#define XSTR3 104           // x staging stride in halves (208B, conflict-free)
#define CH 128              // codes per double-buffered chunk

// Output layout (concatenated flattened outputs, float32):
#define OUT_OFF      0
#define CLOSEST_OFF  4194304
#define LOSS_OFF     4202496
#define PERP_OFF     4202497

// Scratch (no allocations allowed)
__device__ float g_xn[PIXELS * FF];       // normalized projected x, [p][32]
__device__ float g_en[NN * FF];           // normalized codebook, [n][32]
__device__ __half g_xsplit[PIXELS * KS3]; // linear [xh|xh|xm]
// g_esplit is FRAGMENT-ordered: [code-group of 8][kt 0..5][lane 0..31][4 fp16]
// blocks along k: [eh | em | eh]
__device__ __half g_esplit[NN * KS3];
__device__ float g_pval[SPLITS * PIXELS]; // per-split best value
__device__ int   g_pidx[SPLITS * PIXELS]; // per-split best index
__device__ int   g_closest[PIXELS];
__device__ int   g_hist[NN];
__device__ float g_lossp[PIXELS];

// fp32 -> fp16 x2 split (hi 11 bits + mid 11 bits; residual ~2^-22 rel)
__device__ __forceinline__ void split2h(float v, __half& h0, __half& h1)
{
    h0 = __float2half_rn(v);
    float r1 = v - __half2float(h0);
    h1 = __float2half_rn(r1);
}

// ---------------------------------------------------------------------------
// Kernel A: 1x1 conv projection + channel L2 normalize + linear split layout.
// ---------------------------------------------------------------------------
__global__ void proj_norm_kernel(const float* __restrict__ enc,
                                 const float* __restrict__ pw,
                                 const float* __restrict__ pb)
{
    extern __shared__ float sm[];
    float* Ws  = sm;                 // 32*512
    float* xsh = sm + FF * DD;       // 32*33 (padded)
    float* nrm = xsh + 32 * 33;      // 32

    int tid = threadIdx.x;

    const float4* W4 = (const float4*)pw;
    float4* Ws4 = (float4*)Ws;
#pragma unroll
    for (int i = 0; i < 16; i++) Ws4[tid + 256 * i] = W4[tid + 256 * i];
    __syncthreads();

    int lane = tid & 31;     // pixel within tile
    int fg   = tid >> 5;     // 0..7
    int f0   = fg * 4;
    int p    = blockIdx.x * 32 + lane;
    int b    = p >> 10;
    int hw   = p & 1023;

    const float* ep = enc + (size_t)b * DD * HWSZ + hw;
    const float4* w0 = (const float4*)(Ws + (size_t)(f0 + 0) * DD);
    const float4* w1 = (const float4*)(Ws + (size_t)(f0 + 1) * DD);
    const float4* w2 = (const float4*)(Ws + (size_t)(f0 + 2) * DD);
    const float4* w3 = (const float4*)(Ws + (size_t)(f0 + 3) * DD);

    float a0 = 0.f, a1 = 0.f, a2 = 0.f, a3 = 0.f;
#pragma unroll 4
    for (int q = 0; q < 128; q++) {
        float e0 = ep[(4 * q + 0) * HWSZ];
        float e1 = ep[(4 * q + 1) * HWSZ];
        float e2 = ep[(4 * q + 2) * HWSZ];
        float e3 = ep[(4 * q + 3) * HWSZ];
        float4 W0 = w0[q], W1 = w1[q], W2 = w2[q], W3 = w3[q];
        a0 += e0 * W0.x; a0 += e1 * W0.y; a0 += e2 * W0.z; a0 += e3 * W0.w;
        a1 += e0 * W1.x; a1 += e1 * W1.y; a1 += e2 * W1.z; a1 += e3 * W1.w;
        a2 += e0 * W2.x; a2 += e1 * W2.y; a2 += e2 * W2.z; a2 += e3 * W2.w;
        a3 += e0 * W3.x; a3 += e1 * W3.y; a3 += e2 * W3.z; a3 += e3 * W3.w;
    }
    a0 += pb[f0 + 0];
    a1 += pb[f0 + 1];
    a2 += pb[f0 + 2];
    a3 += pb[f0 + 3];

    xsh[lane * 33 + f0 + 0] = a0;
    xsh[lane * 33 + f0 + 1] = a1;
    xsh[lane * 33 + f0 + 2] = a2;
    xsh[lane * 33 + f0 + 3] = a3;
    __syncthreads();

    if (tid < 32) {
        float ss = 0.f;
#pragma unroll
        for (int f = 0; f < 32; f++) { float v = xsh[tid * 33 + f]; ss += v * v; }
        nrm[tid] = fmaxf(sqrtf(ss), 1e-6f);
    }
    __syncthreads();

    float nm = nrm[lane];
    float o[4] = { a0 / nm, a1 / nm, a2 / nm, a3 / nm };
    *(float4*)(g_xn + (size_t)p * FF + f0) = *(float4*)o;

    // X split blocks (linear): [xh | xh | xm]
    __half* xr = g_xsplit + (size_t)p * KS3;
#pragma unroll
    for (int k = 0; k < 4; k++) {
        __half h, m;
        split2h(o[k], h, m);
        int f = f0 + k;
        xr[f]       = h;
        xr[32 + f]  = h;
        xr[64 + f]  = m;
    }
}

// ---------------------------------------------------------------------------
// Kernel B: codebook L2 normalize + FRAGMENT-ordered split store.
// ---------------------------------------------------------------------------
__device__ __forceinline__ void efrag_store(int r, int k_eff, __half v)
{
    int kt  = k_eff >> 4;
    int kr  = k_eff & 15;
    int fl  = (r & 7) * 4 + ((kr & 7) >> 1);
    int el  = (kr >> 3) * 2 + (kr & 1);
    g_esplit[(size_t)(r >> 3) * (NKT * 128) + kt * 128 + fl * 4 + el] = v;
}

__global__ void enorm_kernel(const float* __restrict__ emb)
{
    int tid  = threadIdx.x;
    int r    = blockIdx.x * 8 + (tid >> 5);
    int lane = tid & 31;
    float v = emb[(size_t)r * 32 + lane];
    float ss = v * v;
#pragma unroll
    for (int o = 16; o; o >>= 1) ss += __shfl_xor_sync(0xffffffffu, ss, o);
    float nm = fmaxf(sqrtf(ss), 1e-6f);
    float en = v / nm;
    g_en[(size_t)r * 32 + lane] = en;

    // E split blocks: [eh | em | eh] in fragment order
    __half h, m;
    split2h(en, h, m);
    efrag_store(r, lane, h);
    efrag_store(r, 32 + lane, m);
    efrag_store(r, 64 + lane, h);
}

// ---------------------------------------------------------------------------
// Kernel H: zero histogram (keeps sims in ncu's captured launch slot)
// ---------------------------------------------------------------------------
__global__ void histzero_kernel()
{
    g_hist[blockIdx.x * 256 + threadIdx.x] = 0;
}

// ---------------------------------------------------------------------------
// mma.sync m16n8k16 row.col fp16 -> f32
// ---------------------------------------------------------------------------
__device__ __forceinline__ void mma16816h(float* c, const uint32_t* a,
                                          uint32_t b0, uint32_t b1)
{
    asm volatile(
        "mma.sync.aligned.m16n8k16.row.col.f32.f16.f16.f32 "
        "{%0,%1,%2,%3}, {%4,%5,%6,%7}, {%8,%9}, {%0,%1,%2,%3};"
        : "+f"(c[0]), "+f"(c[1]), "+f"(c[2]), "+f"(c[3])
        : "r"(a[0]), "r"(a[1]), "r"(a[2]), "r"(a[3]), "r"(b0), "r"(b1));
}

__device__ __forceinline__ uint32_t smem_u32c(const void* p) {
    uint32_t a;
    asm("{ .reg .u64 t; cvta.to.shared.u64 t, %1; cvt.u32.u64 %0, t; }"
        : "=r"(a) : "l"(p));
    return a;
}

// ---------------------------------------------------------------------------
// Kernel C (dominant): fp16 3-term split cosine sims on tensor cores.
// 256 thr = 4 pixel-quarter warps x 2 code-half warps. Warp tile 32px x 32
// codes per pass (2 passes per 128-code chunk). K=96 (6 k16 steps).
// A held in 48 regs; B frags single LDS.64; chunks cp.async double-buffered.
// grid (64 px-tiles, 8 splits).
// ---------------------------------------------------------------------------
__global__ void __launch_bounds__(256, 2) sims_argmax_kernel()
{
    extern __shared__ __half smc[];  // 51200B: staging then 2x24576B bufs + merge

    int tid  = threadIdx.x;
    int wid  = tid >> 5;
    int lane = tid & 31;
    int g    = lane >> 2;   // row group / B column
    int kq   = lane & 3;    // k quad
    int cw   = wid >> 2;    // code half of the 128-chunk (0/1)
    int mw   = wid & 3;     // pixel quarter (32 px each)
    int px0  = blockIdx.x * 128;
    int cbase = blockIdx.y * CPS;

    // stage x tile linear: 128 rows x 12 uint4 (192B/row), stride XSTR3 halves
    for (int i = tid; i < 128 * 12; i += 256) {
        int r = i / 12, q = i % 12;
        ((uint4*)(smc + r * XSTR3))[q] =
            ((const uint4*)(g_xsplit + (size_t)(px0 + r) * KS3))[q];
    }
    __syncthreads();

    // extract A fragments once: A[kt][mt][4], held in registers throughout
    uint32_t A[NKT][2][4];
#pragma unroll
    for (int kt = 0; kt < NKT; kt++) {
        int k0 = kt * 16 + kq * 2;
#pragma unroll
        for (int mt = 0; mt < 2; mt++) {
            int r0 = mw * 32 + mt * 16 + g;
            A[kt][mt][0] = *(const uint32_t*)(smc + r0 * XSTR3 + k0);
            A[kt][mt][1] = *(const uint32_t*)(smc + (r0 + 8) * XSTR3 + k0);
            A[kt][mt][2] = *(const uint32_t*)(smc + r0 * XSTR3 + k0 + 8);
            A[kt][mt][3] = *(const uint32_t*)(smc + (r0 + 8) * XSTR3 + k0 + 8);
        }
    }
    __syncthreads();   // staging dead; reuse as double buffers

    uint32_t buf_base = smem_u32c(smc);     // buf0 @ +0, buf1 @ +24576 bytes
    const int CHB = CH * KS3 * 2;           // 24576 bytes per chunk

    // preload chunk 0 into buf0 (each thread copies 6x16B)
    {
        const char* src = (const char*)(g_esplit + (size_t)cbase * KS3);
#pragma unroll
        for (int j = 0; j < 6; j++) {
            uint32_t d = buf_base + (tid + 256 * j) * 16;
            asm volatile("cp.async.ca.shared.global [%0], [%1], 16;"
                         :: "r"(d), "l"(src + (tid + 256 * j) * 16) : "memory");
        }
        asm volatile("cp.async.commit_group;" ::: "memory");
    }

    float bv[4];
    int   bi[4];
#pragma unroll
    for (int s = 0; s < 4; s++) { bv[s] = -3.4e38f; bi[s] = 0; }

    for (int ch = 0; ch < CPS; ch += CH) {
        int cur = (ch >> 7) & 1;
        __syncthreads();   // prev chunk fully consumed before overwrite
        if (ch + CH < CPS) {
            const char* src = (const char*)(g_esplit + (size_t)(cbase + ch + CH) * KS3);
            uint32_t dbase = buf_base + (cur ^ 1) * CHB;
#pragma unroll
            for (int j = 0; j < 6; j++) {
                uint32_t d = dbase + (tid + 256 * j) * 16;
                asm volatile("cp.async.ca.shared.global [%0], [%1], 16;"
                             :: "r"(d), "l"(src + (tid + 256 * j) * 16) : "memory");
            }
            asm volatile("cp.async.commit_group;" ::: "memory");
            asm volatile("cp.async.wait_group 1;" ::: "memory");
        } else {
            asm volatile("cp.async.wait_group 0;" ::: "memory");
        }
        __syncthreads();   // chunk cur visible

        const char* ebuf = (const char*)smc + cur * CHB;

#pragma unroll
        for (int sub = 0; sub < 2; sub++) {
            // this warp's 4 code groups for this pass
            const char* es = ebuf + (cw * 8 + sub * 4) * (NKT * 256);

            float acc[4][2][4];
#pragma unroll
            for (int nt = 0; nt < 4; nt++)
#pragma unroll
                for (int mt = 0; mt < 2; mt++)
#pragma unroll
                    for (int c = 0; c < 4; c++) acc[nt][mt][c] = 0.f;

#pragma unroll
            for (int kt = 0; kt < NKT; kt++) {
#pragma unroll
                for (int nt = 0; nt < 4; nt++) {
                    uint2 bb = *(const uint2*)(es + nt * (NKT * 256)
                                               + kt * 256 + lane * 8);
                    mma16816h(acc[nt][0], A[kt][0], bb.x, bb.y);
                    mma16816h(acc[nt][1], A[kt][1], bb.x, bb.y);
                }
            }

            // argmax update; ascending code order within this warp's share
#pragma unroll
            for (int nt = 0; nt < 4; nt++) {
                int c0 = cbase + ch + cw * 64 + sub * 32 + nt * 8 + kq * 2;
#pragma unroll
                for (int mt = 0; mt < 2; mt++) {
#pragma unroll
                    for (int h = 0; h < 2; h++) {
                        int s = mt * 2 + h;
                        float v0 = acc[nt][mt][h * 2 + 0];
                        float v1 = acc[nt][mt][h * 2 + 1];
                        if (v0 > bv[s]) { bv[s] = v0; bi[s] = c0; }
                        if (v1 > bv[s]) { bv[s] = v1; bi[s] = c0 + 1; }
                    }
                }
            }
        }
    }

    // reduce across the 4 kq lanes (lower index wins ties)
#pragma unroll
    for (int s = 0; s < 4; s++) {
#pragma unroll
        for (int o = 1; o <= 2; o <<= 1) {
            float ov = __shfl_xor_sync(0xffffffffu, bv[s], o);
            int   oi = __shfl_xor_sync(0xffffffffu, bi[s], o);
            if (ov > bv[s] || (ov == bv[s] && oi < bi[s])) { bv[s] = ov; bi[s] = oi; }
        }
    }

    // merge the two code-half warps per pixel via smem (bytes 49152..51200)
    float* sv = (float*)((char*)smc + 49152);   // [2][128]
    int*   si = (int*)(sv + 256);               // [2][128]
    __syncthreads();
    if (kq == 0) {
#pragma unroll
        for (int s = 0; s < 4; s++) {
            int mt = s >> 1, h = s & 1;
            int pix = mw * 32 + mt * 16 + h * 8 + g;
            sv[cw * 128 + pix] = bv[s];
            si[cw * 128 + pix] = bi[s];
        }
    }
    __syncthreads();
    if (tid < 128) {
        float v0 = sv[tid];       int i0 = si[tid];
        float v1 = sv[128 + tid]; int i1 = si[128 + tid];
        if (v1 > v0 || (v1 == v0 && i1 < i0)) { v0 = v1; i0 = i1; }
        g_pval[blockIdx.y * PIXELS + px0 + tid] = v0;
        g_pidx[blockIdx.y * PIXELS + px0 + tid] = i0;
    }
}

// ---------------------------------------------------------------------------
// Kernel F: reduce split partials -> closest; histogram; per-pixel loss partial.
// ---------------------------------------------------------------------------
__global__ void reduce_kernel(float* __restrict__ out)
{
    int p = blockIdx.x * 256 + threadIdx.x;
    float bv = -3.4e38f;
    int   bi = 0x7fffffff;
#pragma unroll
    for (int s = 0; s < SPLITS; s++) {
        float v = g_pval[s * PIXELS + p];
        int  ix = g_pidx[s * PIXELS + p];
        if (v > bv || (v == bv && ix < bi)) { bv = v; bi = ix; }
    }
    g_closest[p] = bi;
    out[CLOSEST_OFF + p] = (float)bi;
    atomicAdd(&g_hist[bi], 1);

    float s2 = 0.f;
    const float4* xr = (const float4*)(g_xn + (size_t)p * 32);
    const float4* er = (const float4*)(g_en + (size_t)bi * 32);
#pragma unroll
    for (int q = 0; q < 8; q++) {
        float4 x = xr[q], e = er[q];
        float d0 = x.x - e.x, d1 = x.y - e.y, d2 = x.z - e.z, d3 = x.w - e.w;
        s2 += d0 * d0; s2 += d1 * d1; s2 += d2 * d2; s2 += d3 * d3;
    }
    g_lossp[p] = s2;
}

// ---------------------------------------------------------------------------
// Kernel D: expansion GEMM: out[b,d,hw] = sum_f lat[p][f] * exp_w[d][f] + exp_b[d]
// ---------------------------------------------------------------------------
__global__ void expand_kernel(const float* __restrict__ ew,
                              const float* __restrict__ eb,
                              float* __restrict__ out)
{
    __shared__ float Wsh[64 * 32];
    __shared__ float bsh[64];
    int tid = threadIdx.x;
    int d0  = blockIdx.y * 64;

    const float4* src = (const float4*)(ew + (size_t)d0 * 32);
    float4* dst = (float4*)Wsh;
    dst[tid]       = src[tid];
    dst[tid + 256] = src[tid + 256];
    if (tid < 64) bsh[tid] = eb[d0 + tid];
    __syncthreads();

    int p  = blockIdx.x * 256 + tid;
    int b  = p >> 10;
    int hw = p & 1023;
    int idx = g_closest[p];

    float4 lat[8];
    const float4* lr = (const float4*)(g_en + (size_t)idx * 32);
#pragma unroll
    for (int q = 0; q < 8; q++) lat[q] = lr[q];

    float* outp = out + OUT_OFF + ((size_t)b * 512 + d0) * 1024 + hw;
#pragma unroll 2
    for (int dd = 0; dd < 64; dd++) {
        const float4* wr = (const float4*)(Wsh + dd * 32);
        float s = bsh[dd];
#pragma unroll
        for (int q = 0; q < 8; q++) {
            float4 w = wr[q];
            s += lat[q].x * w.x; s += lat[q].y * w.y;
            s += lat[q].z * w.z; s += lat[q].w * w.w;
        }
        outp[(size_t)dd * 1024] = s;
    }
}

// ---------------------------------------------------------------------------
// Kernel G: deterministic final reductions -> loss_q, perplexity
// ---------------------------------------------------------------------------
__global__ void finalize_kernel(float* __restrict__ out)
{
    __shared__ double sh[256];
    int tid = threadIdx.x;

    double ls = 0.0;
    for (int i = tid; i < PIXELS; i += 256) ls += (double)g_lossp[i];
    sh[tid] = ls;
    __syncthreads();
    for (int o = 128; o; o >>= 1) {
        if (tid < o) sh[tid] += sh[tid + o];
        __syncthreads();
    }
    double loss = sh[0] / (double)(PIXELS * 32);
    __syncthreads();

    double ps = 0.0;
    for (int i = tid; i < NN; i += 256) {
        float u = (float)g_hist[i] * (1.0f / 8192.0f);
        ps += -(double)u * log((double)u + 1e-6);
    }
    sh[tid] = ps;
    __syncthreads();
    for (int o = 128; o; o >>= 1) {
        if (tid < o) sh[tid] += sh[tid + o];
        __syncthreads();
    }
    if (tid == 0) {
        out[LOSS_OFF] = (float)loss;
        out[PERP_OFF] = (float)exp(sh[0]);
    }
}

// ---------------------------------------------------------------------------
extern "C" void kernel_launch(void* const* d_in, const int* in_sizes, int n_in,
                              void* d_out, int out_size)
{
    const float* enc = (const float*)d_in[0];  // [8,512,32,32]
    const float* emb = (const float*)d_in[1];  // [16384,32]
    const float* pw  = (const float*)d_in[2];  // [32,512]
    const float* pb  = (const float*)d_in[3];  // [32]
    const float* ew  = (const float*)d_in[4];  // [512,32]
    const float* eb  = (const float*)d_in[5];  // [512]
    float* out = (float*)d_out;

    (void)in_sizes; (void)n_in; (void)out_size;

    const int a_smem = (FF * DD + 32 * 33 + 32) * (int)sizeof(float); // 69888
    cudaFuncSetAttribute(proj_norm_kernel,
                         cudaFuncAttributeMaxDynamicSharedMemorySize, a_smem);

    const int c_smem = 51200;  // 2x24576 chunk buffers + 2048 merge
    cudaFuncSetAttribute(sims_argmax_kernel,
                         cudaFuncAttributeMaxDynamicSharedMemorySize, c_smem);

    proj_norm_kernel<<<256, 256, a_smem>>>(enc, pw, pb);
    enorm_kernel<<<2048, 256>>>(emb);
    histzero_kernel<<<64, 256>>>();
    sims_argmax_kernel<<<dim3(64, SPLITS), 256, c_smem>>>();
    reduce_kernel<<<32, 256>>>(out);
    expand_kernel<<<dim3(32, 8), 256>>>(ew, eb, out);
    finalize_kernel<<<1, 256>>>(out);
}